// round 14
// baseline (speedup 1.0000x reference)
#include <cuda_runtime.h>

// ---------------------------------------------------------------------------
// TopographLoss: B=1, C=2, D=64, H=112, W=112
// paired = bin_pred + 2*bin_gt in {0:TN, 1:FP, 2:FN, 3:TP}
// CCL: 6-conn for cat 0, 26-conn otherwise. Label = min voxel index of comp.
// Pipeline: hook (backward min) -> Jacobi label-min pass -> CAS union
// (L1-cached finds; CAS provides freshness) -> flatten -> fused
// fixpoint-check + wrapped-edge pass -> insurance props + guarded edge redo.
//
// CRITICAL-REGION TEST EMULATES THE REFERENCE AS EXECUTED (jax x64 DISABLED):
// edge keys L*N+nl wrap in int32; SENT canonicalizes to N*N mod 2^32 = 2^28
// (N = 49*2^14). Only wrapped keys in [0, 2^28) survive; src=k/N in [0,334],
// dst=k%N decodes to a garbage voxel for wrapped keys; category from
// paired[dst]. Components with label > 334 are always critical.
// distinct-count==1 tested via min==max (dedup-invariant).
// Loss = mean over critical components of mean_{voxels in comp}(p - g)^2.
// ---------------------------------------------------------------------------

#define DD 64
#define HH 112
#define WW 112
#define NN (DD * HH * WW)        // 802816 = 3136 * 256 exactly
#define IMAX 0x7fffffff
#define SENTW 268435456u         // (N*N) mod 2^32 = 2^28
#define SMAX 336                 // surviving src ids are in [0,334]

// ---- device scratch (no allocations allowed) ----
__device__ int            g_parent[NN];   // per-voxel component label (min idx)
__device__ unsigned char  g_paired[NN];
__device__ int            g_tpmin[SMAX];  // per-src wrapped-edge dst min/max
__device__ int            g_tpmax[SMAX];
__device__ int            g_tnmin[SMAX];
__device__ int            g_tnmax[SMAX];
__device__ float          g_lsum[NN];
__device__ int            g_ccnt[NN];
__device__ float          g_regsum;
__device__ int            g_nreg;
__device__ int            g_flag[4];      // repair flags per insurance stage

// ---------------------------------------------------------------------------
// K1: binarize -> paired; zero accumulators; init small arrays and flags
// ---------------------------------------------------------------------------
__global__ void k_init(const float* __restrict__ pred, const int* __restrict__ tgt) {
    int i = blockIdx.x * blockDim.x + threadIdx.x;   // exact grid
    float p0 = pred[i];
    float p1 = pred[NN + i];
    int bp = (p1 > p0) ? 1 : 0;              // argmax over C: tie -> channel 0
    int bg = (tgt[i] == 1) ? 1 : 0;
    g_paired[i] = (unsigned char)(bp + 2 * bg);
    g_lsum[i] = 0.0f;
    g_ccnt[i] = 0;
    if (i < SMAX) {
        g_tpmin[i] = IMAX; g_tnmin[i] = IMAX;
        g_tpmax[i] = -1;   g_tnmax[i] = -1;
    }
    if (i == 0) { g_regsum = 0.0f; g_nreg = 0; }
    if (i < 4) g_flag[i] = 0;
}

// ---------------------------------------------------------------------------
// K2: atomics-free hooking init. parent[i] = min same-cat BACKWARD neighbor
// (j < i guaranteed), else i. All links genuine same-component edges.
// ---------------------------------------------------------------------------
__global__ void k_hook() {
    int i = blockIdx.x * blockDim.x + threadIdx.x;   // exact grid
    int x = i % WW;
    int t = i / WW;
    int y = t % HH;
    int z = t / HH;
    int ci = g_paired[i];

    const int off[13][3] = {   // backward: j < i always
        {-1,-1,-1},{-1,-1,0},{-1,-1,1},
        {-1,0,-1},{-1,0,0},{-1,0,1},
        {-1,1,-1},{-1,1,0},{-1,1,1},
        {0,-1,-1},{0,-1,0},{0,-1,1},
        {0,0,-1}};
    const bool axis[13] = {false,false,false,
                           false,true,false,
                           false,false,false,
                           false,true,false,
                           true};
    int best = i;
#pragma unroll
    for (int k = 0; k < 13; k++) {
        int zz = z + off[k][0];
        int yy = y + off[k][1];
        int xx = x + off[k][2];
        if ((unsigned)zz < DD && (unsigned)yy < HH && (unsigned)xx < WW) {
            int j = (zz * HH + yy) * WW + xx;
            if (g_paired[j] == ci && (ci != 0 || axis[k])) {
                if (j < best) best = j;
            }
        }
    }
    g_parent[i] = best;
}

// ---------------------------------------------------------------------------
// K3: Jacobi label-min pass (atomics-free). parent[i] = min(parent[i],
// parent[parent[i]], min over same-cat neighbors of parent[j]). Each thread
// writes ONLY its own entry -> race-free. Every candidate is a genuine
// same-component index < i (or i itself) -> forest invariants preserved.
// Coalesces basins before the CAS union phase.
// ---------------------------------------------------------------------------
__global__ void k_jmin() {
    int i = blockIdx.x * blockDim.x + threadIdx.x;   // exact grid
    int x = i % WW;
    int t = i / WW;
    int y = t % HH;
    int z = t / HH;
    int ci = g_paired[i];
    int cur = g_parent[i];
    int best = g_parent[cur];      // jump (same-component, <= cur)

    const int off[26][3] = {
        {-1,-1,-1},{-1,-1,0},{-1,-1,1},{-1,0,-1},{-1,0,0},{-1,0,1},
        {-1,1,-1},{-1,1,0},{-1,1,1},
        {0,-1,-1},{0,-1,0},{0,-1,1},{0,0,-1},{0,0,1},
        {0,1,-1},{0,1,0},{0,1,1},
        {1,-1,-1},{1,-1,0},{1,-1,1},{1,0,-1},{1,0,0},{1,0,1},
        {1,1,-1},{1,1,0},{1,1,1}};
    const bool axis[26] = {
        false,false,false,false,true,false,false,false,false,
        false,true,false,true,true,false,true,false,
        false,false,false,false,true,false,false,false,false};
#pragma unroll
    for (int k = 0; k < 26; k++) {
        int zz = z + off[k][0];
        int yy = y + off[k][1];
        int xx = x + off[k][2];
        if ((unsigned)zz < DD && (unsigned)yy < HH && (unsigned)xx < WW) {
            int j = (zz * HH + yy) * WW + xx;
            if (g_paired[j] == ci && (ci != 0 || axis[k])) {
                int lj = g_parent[j];
                if (lj < best) best = lj;
            }
        }
    }
    if (best < cur) g_parent[i] = best;
}

// ---------------------------------------------------------------------------
// Union-find with PLAIN (L1-cached) loads in find. Safety:
//  * any stored parent value is a genuine same-component ancestor with
//    strictly smaller index -> stale finds terminate at a true past-rep;
//  * ra == rb (even stale) proves connectivity -> safe skip;
//  * progress relies ONLY on atomicCAS return values (coherent, strictly
//    decreasing per retry) -> no livelock, no lost unions.
// Min-hooking: final root of each component is its min voxel index.
// ---------------------------------------------------------------------------
__device__ __forceinline__ int find_root(int x) {
    while (true) {
        int p = g_parent[x];
        if (p == x) return x;
        int gp = g_parent[p];
        if (gp == p) return p;
        g_parent[x] = gp;   // path halving hint (benign, same-component)
        x = gp;
    }
}
__device__ __forceinline__ int unite_roots(int ra, int rb) {
    while (ra != rb) {
        if (ra > rb) { int t = ra; ra = rb; rb = t; }
        int old = atomicCAS(&g_parent[rb], rb, ra);  // coherent
        if (old == rb || old == ra) return ra;
        rb = find_root(old);
        ra = find_root(ra);
    }
    return ra;
}

// K4: union over ALL 13 forward edges per voxel (full edge coverage).
// Root of i found lazily once and maintained via unite_roots' return.
__global__ void k_union() {
    int i = blockIdx.x * blockDim.x + threadIdx.x;   // exact grid
    int x = i % WW;
    int t = i / WW;
    int y = t % HH;
    int z = t / HH;
    int ci = g_paired[i];
    int ri = -1;

    const int off[13][3] = {   // forward: j > i always
        {0,0,1},{0,1,-1},{0,1,0},{0,1,1},
        {1,-1,-1},{1,-1,0},{1,-1,1},
        {1,0,-1},{1,0,0},{1,0,1},
        {1,1,-1},{1,1,0},{1,1,1}};
    const bool axis[13] = {true,false,true,false,
                           false,false,false,
                           false,true,false,
                           false,false,false};
#pragma unroll
    for (int e = 0; e < 13; e++) {
        int zz = z + off[e][0];
        int yy = y + off[e][1];
        int xx = x + off[e][2];
        if ((unsigned)zz < DD && (unsigned)yy < HH && (unsigned)xx < WW) {
            int j = (zz * HH + yy) * WW + xx;
            if (g_paired[j] == ci && (ci != 0 || axis[e])) {
                int pj = g_parent[j];
                if (pj == ri) continue;              // same component already
                if (ri < 0) ri = find_root(i);
                if (pj == ri) continue;
                int rj = find_root(j);
                if (rj != ri) ri = unite_roots(ri, rj);
            }
        }
    }
}

// K5: flatten parent pointers to roots (forest final after union)
__global__ void k_flatten() {
    int i = blockIdx.x * blockDim.x + threadIdx.x;   // exact grid
    int x = i;
    int p = g_parent[x];
    while (p != x) { x = p; p = g_parent[x]; }
    g_parent[i] = x;
}

// ---------------------------------------------------------------------------
// K6 (fused): fixpoint-check (min-prop insurance, iteration 0) + wrapped
// edge accumulation, sharing one 26-neighbor stencil read.
//  * check: label-min over same-cat neighbors + pointer jump; any repair
//    does atomicMin and raises g_flag[1] (UF can only split, so the min-prop
//    fixpoint provably equals the true labels; empirically no repair fires).
//  * edges: for different-label neighbor pairs, emulate int32-wrapped keys
//    (early gate on base = L*N mod 2^32). If a repair fired anywhere, the
//    guarded fix kernels below redo the edge pass on final labels.
// ---------------------------------------------------------------------------
__global__ void k_edge_check() {
    int i = blockIdx.x * blockDim.x + threadIdx.x;   // exact grid
    int x = i % WW;
    int t = i / WW;
    int y = t % HH;
    int z = t / HH;
    int ci = g_paired[i];
    int L = g_parent[i];
    int best = L;
    unsigned base = (unsigned)L * (unsigned)NN;
    bool edge_on = (base < SENTW) || (base >= (0xFFFFFFFFu - (unsigned)NN));

    const int off[26][3] = {
        {-1,-1,-1},{-1,-1,0},{-1,-1,1},{-1,0,-1},{-1,0,0},{-1,0,1},
        {-1,1,-1},{-1,1,0},{-1,1,1},
        {0,-1,-1},{0,-1,0},{0,-1,1},{0,0,-1},{0,0,1},
        {0,1,-1},{0,1,0},{0,1,1},
        {1,-1,-1},{1,-1,0},{1,-1,1},{1,0,-1},{1,0,0},{1,0,1},
        {1,1,-1},{1,1,0},{1,1,1}};
    const bool axis[26] = {
        false,false,false,false,true,false,false,false,false,
        false,true,false,true,true,false,true,false,
        false,false,false,false,true,false,false,false,false};
#pragma unroll
    for (int k = 0; k < 26; k++) {
        int zz = z + off[k][0];
        int yy = y + off[k][1];
        int xx = x + off[k][2];
        if ((unsigned)zz < DD && (unsigned)yy < HH && (unsigned)xx < WW) {
            int j = (zz * HH + yy) * WW + xx;
            int nl = g_parent[j];
            // fixpoint check (same category only)
            if (g_paired[j] == ci && (ci != 0 || axis[k])) {
                if (nl < best) best = nl;
            }
            // wrapped-edge accumulation (different labels, any category)
            if (edge_on && nl != L) {
                unsigned kw = base + (unsigned)nl;       // wraps mod 2^32
                if (kw < SENTW) {
                    int s = (int)(kw / (unsigned)NN);    // <= 334
                    int d = (int)(kw % (unsigned)NN);
                    int cat = g_paired[d];
                    if (cat == 3) {
                        if (d < g_tpmin[s]) atomicMin(&g_tpmin[s], d);
                        if (d > g_tpmax[s]) atomicMax(&g_tpmax[s], d);
                    } else if (cat == 0) {
                        if (d < g_tnmin[s]) atomicMin(&g_tnmin[s], d);
                        if (d > g_tnmax[s]) atomicMax(&g_tnmax[s], d);
                    }
                }
            }
        }
    }
    int jc = g_parent[L];          // pointer jump (same-component index)
    if (jc < best) best = jc;
    if (best < L) {                // lost union -> repair + raise flag
        atomicMin(&g_parent[i], best);
        g_flag[1] = 1;
    }
}

// K7: insurance min-prop iterations (early-exit when no repair occurred)
__global__ void k_prop(int it) {
    if (g_flag[it] == 0) return;
    int i = blockIdx.x * blockDim.x + threadIdx.x;   // exact grid
    int x = i % WW;
    int t = i / WW;
    int y = t % HH;
    int z = t / HH;
    int ci = g_paired[i];
    int cur = g_parent[i];
    int best = cur;

    const int off[26][3] = {
        {-1,-1,-1},{-1,-1,0},{-1,-1,1},{-1,0,-1},{-1,0,0},{-1,0,1},
        {-1,1,-1},{-1,1,0},{-1,1,1},
        {0,-1,-1},{0,-1,0},{0,-1,1},{0,0,-1},{0,0,1},
        {0,1,-1},{0,1,0},{0,1,1},
        {1,-1,-1},{1,-1,0},{1,-1,1},{1,0,-1},{1,0,0},{1,0,1},
        {1,1,-1},{1,1,0},{1,1,1}};
    const bool axis[26] = {
        false,false,false,false,true,false,false,false,false,
        false,true,false,true,true,false,true,false,
        false,false,false,false,true,false,false,false,false};
#pragma unroll
    for (int k = 0; k < 26; k++) {
        int zz = z + off[k][0];
        int yy = y + off[k][1];
        int xx = x + off[k][2];
        if ((unsigned)zz < DD && (unsigned)yy < HH && (unsigned)xx < WW) {
            int j = (zz * HH + yy) * WW + xx;
            if (g_paired[j] == ci && (ci != 0 || axis[k])) {
                int lj = g_parent[j];
                if (lj < best) best = lj;
            }
        }
    }
    int jc = g_parent[cur];
    if (jc < best) best = jc;
    if (best < cur) {
        atomicMin(&g_parent[i], best);
        g_flag[it + 1] = 1;
    }
}

// K8/K9: guarded edge redo if any repair fired (labels changed after the
// fused pass). Inactive in the expected case (~3us each).
__global__ void k_fixzero() {
    if (g_flag[1] == 0) return;
    int i = threadIdx.x;
    if (i < SMAX) {
        g_tpmin[i] = IMAX; g_tnmin[i] = IMAX;
        g_tpmax[i] = -1;   g_tnmax[i] = -1;
    }
}
__global__ void k_edges_fix() {
    if (g_flag[1] == 0) return;
    int i = blockIdx.x * blockDim.x + threadIdx.x;   // exact grid
    int L = g_parent[i];
    unsigned base = (unsigned)L * (unsigned)NN;
    if (base >= SENTW && base < (0xFFFFFFFFu - (unsigned)NN)) return;
    int x = i % WW;
    int t = i / WW;
    int y = t % HH;
    int z = t / HH;
#pragma unroll
    for (int dz = -1; dz <= 1; dz++)
#pragma unroll
        for (int dy = -1; dy <= 1; dy++)
#pragma unroll
            for (int dx = -1; dx <= 1; dx++) {
                if (dz == 0 && dy == 0 && dx == 0) continue;
                int zz = z + dz, yy = y + dy, xx = x + dx;
                if ((unsigned)zz < DD && (unsigned)yy < HH && (unsigned)xx < WW) {
                    int j = (zz * HH + yy) * WW + xx;
                    int nl = g_parent[j];
                    if (nl != L) {
                        unsigned kw = base + (unsigned)nl;
                        if (kw < SENTW) {
                            int s = (int)(kw / (unsigned)NN);
                            int d = (int)(kw % (unsigned)NN);
                            int cat = g_paired[d];
                            if (cat == 3) {
                                if (d < g_tpmin[s]) atomicMin(&g_tpmin[s], d);
                                if (d > g_tpmax[s]) atomicMax(&g_tpmax[s], d);
                            } else if (cat == 0) {
                                if (d < g_tnmin[s]) atomicMin(&g_tnmin[s], d);
                                if (d > g_tnmax[s]) atomicMax(&g_tnmax[s], d);
                            }
                        }
                    }
                }
            }
}

// ---------------------------------------------------------------------------
// K10: critical voxels -> per-label (sum of (p-g)^2, count), warp-aggregated
// via match groups; reduction iterates only the group's set bits (legal:
// every lane of a group has the same mask and trip count).
// ---------------------------------------------------------------------------
__global__ void k_crit(const float* __restrict__ pred) {
    int i = blockIdx.x * blockDim.x + threadIdx.x;   // exact grid
    int c = g_paired[i];
    bool crit = false;
    int li = -1;
    float v = 0.0f;
    if (c == 1 || c == 2) {
        li = g_parent[i];
        bool ok = false;
        if (li < SMAX)
            ok = (g_tpmin[li] == g_tpmax[li]) && (g_tnmin[li] == g_tnmax[li]);
        if (!ok) {
            float p0 = pred[i];
            float p1 = pred[NN + i];
            float m  = fmaxf(p0, p1);
            float e0 = expf(p0 - m);
            float e1 = expf(p1 - m);
            float p  = e1 / (e0 + e1);
            float g = (c == 2) ? 1.0f : 0.0f;
            float d = p - g;
            v = d * d;
            crit = true;
        }
    }
    int key = crit ? li : -1;
    unsigned grp = __match_any_sync(0xffffffffu, key);
    if (crit) {
        int lane = threadIdx.x & 31;
        int leader = __ffs(grp) - 1;
        float sum = v;
        int cnt = __popc(grp);
        unsigned m = grp & ~(1u << lane);
        while (m) {                         // |grp|-1 iterations, same for all
            int l = __ffs(m) - 1;
            m &= m - 1;
            sum += __shfl_sync(grp, v, l);
        }
        if (lane == leader) {
            atomicAdd(&g_lsum[key], sum);
            atomicAdd(&g_ccnt[key], cnt);
        }
    }
}

// ---------------------------------------------------------------------------
// K11: reg_sum = sum lsum/ccnt over critical labels; n_reg = #(ccnt>0)
// ---------------------------------------------------------------------------
__global__ void k_reduce() {
    __shared__ float ssum[256];
    __shared__ int   scnt[256];
    int i = blockIdx.x * blockDim.x + threadIdx.x;
    float rs = 0.0f;
    int nr = 0;
    int cc = g_ccnt[i];
    if (cc > 0) { rs = g_lsum[i] / (float)cc; nr = 1; }
    ssum[threadIdx.x] = rs;
    scnt[threadIdx.x] = nr;
    __syncthreads();
    for (int s = 128; s > 0; s >>= 1) {
        if (threadIdx.x < s) {
            ssum[threadIdx.x] += ssum[threadIdx.x + s];
            scnt[threadIdx.x] += scnt[threadIdx.x + s];
        }
        __syncthreads();
    }
    if (threadIdx.x == 0) {
        if (ssum[0] != 0.0f) atomicAdd(&g_regsum, ssum[0]);
        if (scnt[0] != 0)    atomicAdd(&g_nreg, scnt[0]);
    }
}

__global__ void k_final(float* out) {
    if (threadIdx.x == 0 && blockIdx.x == 0) {
        int n = g_nreg;
        out[0] = (n > 0) ? (g_regsum / (float)n) : 0.0f;
    }
}

// ---------------------------------------------------------------------------
extern "C" void kernel_launch(void* const* d_in, const int* in_sizes, int n_in,
                              void* d_out, int out_size) {
    const float* pred = (const float*)d_in[0];   // (1,2,64,112,112) float32
    const int*   tgt  = (const int*)d_in[1];     // (1,64,112,112) int32
    if (n_in >= 2 && in_sizes[0] == NN && in_sizes[1] == 2 * NN) {
        pred = (const float*)d_in[1];
        tgt  = (const int*)d_in[0];
    }
    float* out = (float*)d_out;

    const int T = 256;
    const int G = NN / T;          // 3136, exact

    k_init<<<G, T>>>(pred, tgt);   // 1
    k_hook<<<G, T>>>();            // 2
    k_jmin<<<G, T>>>();            // 3
    k_union<<<G, T>>>();           // 4  <- profiled slot
    k_flatten<<<G, T>>>();         // 5
    k_edge_check<<<G, T>>>();      // 6  (fused fixpoint check + edges)
    k_prop<<<G, T>>>(1);           // 7  insurance (early-exit)
    k_prop<<<G, T>>>(2);           // 8  insurance (early-exit)
    k_fixzero<<<1, 512>>>();       // 9  guarded
    k_edges_fix<<<G, T>>>();       // 10 guarded
    k_crit<<<G, T>>>(pred);        // 11
    k_reduce<<<G, T>>>();          // 12
    k_final<<<1, 32>>>(out);       // 13
}

// round 15
// speedup vs baseline: 1.1637x; 1.1637x over previous
#include <cuda_runtime.h>

// ---------------------------------------------------------------------------
// TopographLoss: B=1, C=2, D=64, H=112, W=112
// paired = bin_pred + 2*bin_gt in {0:TN, 1:FP, 2:FN, 3:TP}
// CCL: 6-conn for cat 0, 26-conn otherwise. Label = min voxel index of comp.
// Pipeline: hook (backward min) -> flatten -> CAS union (L1-cached finds,
// eager root seed + find memo) -> flatten -> fused fixpoint-check +
// wrapped-edge pass -> insurance props + guarded edge redo.
//
// CRITICAL-REGION TEST EMULATES THE REFERENCE AS EXECUTED (jax x64 DISABLED):
// edge keys L*N+nl wrap in int32; SENT canonicalizes to N*N mod 2^32 = 2^28
// (N = 49*2^14). Only wrapped keys in [0, 2^28) survive; src=k/N in [0,334],
// dst=k%N decodes to a garbage voxel for wrapped keys; category from
// paired[dst]. Components with label > 334 are always critical.
// distinct-count==1 tested via min==max (dedup-invariant).
// Loss = mean over critical components of mean_{voxels in comp}(p - g)^2.
// ---------------------------------------------------------------------------

#define DD 64
#define HH 112
#define WW 112
#define NN (DD * HH * WW)        // 802816 = 3136 * 256 exactly
#define IMAX 0x7fffffff
#define SENTW 268435456u         // (N*N) mod 2^32 = 2^28
#define SMAX 336                 // surviving src ids are in [0,334]

// ---- device scratch (no allocations allowed) ----
__device__ int            g_parent[NN];   // per-voxel component label (min idx)
__device__ unsigned char  g_paired[NN];
__device__ int            g_tpmin[SMAX];  // per-src wrapped-edge dst min/max
__device__ int            g_tpmax[SMAX];
__device__ int            g_tnmin[SMAX];
__device__ int            g_tnmax[SMAX];
__device__ float          g_lsum[NN];
__device__ int            g_ccnt[NN];
__device__ float          g_regsum;
__device__ int            g_nreg;
__device__ int            g_flag[4];      // repair flags per insurance stage

// ---------------------------------------------------------------------------
// K1: binarize -> paired; zero accumulators; init small arrays and flags
// ---------------------------------------------------------------------------
__global__ void k_init(const float* __restrict__ pred, const int* __restrict__ tgt) {
    int i = blockIdx.x * blockDim.x + threadIdx.x;   // exact grid
    float p0 = pred[i];
    float p1 = pred[NN + i];
    int bp = (p1 > p0) ? 1 : 0;              // argmax over C: tie -> channel 0
    int bg = (tgt[i] == 1) ? 1 : 0;
    g_paired[i] = (unsigned char)(bp + 2 * bg);
    g_lsum[i] = 0.0f;
    g_ccnt[i] = 0;
    if (i < SMAX) {
        g_tpmin[i] = IMAX; g_tnmin[i] = IMAX;
        g_tpmax[i] = -1;   g_tnmax[i] = -1;
    }
    if (i == 0) { g_regsum = 0.0f; g_nreg = 0; }
    if (i < 4) g_flag[i] = 0;
}

// ---------------------------------------------------------------------------
// K2: atomics-free hooking init. parent[i] = min same-cat BACKWARD neighbor
// (j < i guaranteed), else i. All links genuine same-component edges.
// ---------------------------------------------------------------------------
__global__ void k_hook() {
    int i = blockIdx.x * blockDim.x + threadIdx.x;   // exact grid
    int x = i % WW;
    int t = i / WW;
    int y = t % HH;
    int z = t / HH;
    int ci = g_paired[i];

    const int off[13][3] = {   // backward: j < i always
        {-1,-1,-1},{-1,-1,0},{-1,-1,1},
        {-1,0,-1},{-1,0,0},{-1,0,1},
        {-1,1,-1},{-1,1,0},{-1,1,1},
        {0,-1,-1},{0,-1,0},{0,-1,1},
        {0,0,-1}};
    const bool axis[13] = {false,false,false,
                           false,true,false,
                           false,false,false,
                           false,true,false,
                           true};
    int best = i;
#pragma unroll
    for (int k = 0; k < 13; k++) {
        int zz = z + off[k][0];
        int yy = y + off[k][1];
        int xx = x + off[k][2];
        if ((unsigned)zz < DD && (unsigned)yy < HH && (unsigned)xx < WW) {
            int j = (zz * HH + yy) * WW + xx;
            if (g_paired[j] == ci && (ci != 0 || axis[k])) {
                if (j < best) best = j;
            }
        }
    }
    g_parent[i] = best;
}

// ---------------------------------------------------------------------------
// Union-find with PLAIN (L1-cached) loads in find. Safety:
//  * any stored parent value is a genuine same-component ancestor with
//    strictly smaller index -> stale finds terminate at a true past-rep;
//  * ra == rb (even stale) proves connectivity -> safe skip;
//  * progress relies ONLY on atomicCAS return values (coherent, strictly
//    decreasing per retry) -> no livelock, no lost unions.
// Min-hooking: final root of each component is its min voxel index.
// ---------------------------------------------------------------------------
__device__ __forceinline__ int find_root(int x) {
    while (true) {
        int p = g_parent[x];
        if (p == x) return x;
        int gp = g_parent[p];
        if (gp == p) return p;
        g_parent[x] = gp;   // path halving hint (benign, same-component)
        x = gp;
    }
}
__device__ __forceinline__ int unite_roots(int ra, int rb) {
    while (ra != rb) {
        if (ra > rb) { int t = ra; ra = rb; rb = t; }
        int old = atomicCAS(&g_parent[rb], rb, ra);  // coherent
        if (old == rb || old == ra) return ra;
        rb = find_root(old);
        ra = find_root(ra);
    }
    return ra;
}

// K3: flatten parent pointers (pointer jumping to current roots)
__global__ void k_flatten() {
    int i = blockIdx.x * blockDim.x + threadIdx.x;   // exact grid
    int x = i;
    int p = g_parent[x];
    while (p != x) { x = p; p = g_parent[x]; }
    g_parent[i] = x;
}

// K4: union over ALL 13 forward edges per voxel (full edge coverage).
// Post-flatten, g_parent[i] IS the basin root -> eager seed, no initial find.
// 1-entry memo (pj -> rj): neighbors usually share 1-3 basins; memoized
// values are genuine same-component representatives (unite re-finds), so
// staleness is harmless.
__global__ void k_union() {
    int i = blockIdx.x * blockDim.x + threadIdx.x;   // exact grid
    int x = i % WW;
    int t = i / WW;
    int y = t % HH;
    int z = t / HH;
    int ci = g_paired[i];
    int ri = g_parent[i];              // post-flatten: the basin root
    int memo_p = -1, memo_r = -1;

    const int off[13][3] = {   // forward: j > i always
        {0,0,1},{0,1,-1},{0,1,0},{0,1,1},
        {1,-1,-1},{1,-1,0},{1,-1,1},
        {1,0,-1},{1,0,0},{1,0,1},
        {1,1,-1},{1,1,0},{1,1,1}};
    const bool axis[13] = {true,false,true,false,
                           false,false,false,
                           false,true,false,
                           false,false,false};
#pragma unroll
    for (int e = 0; e < 13; e++) {
        int zz = z + off[e][0];
        int yy = y + off[e][1];
        int xx = x + off[e][2];
        if ((unsigned)zz < DD && (unsigned)yy < HH && (unsigned)xx < WW) {
            int j = (zz * HH + yy) * WW + xx;
            if (g_paired[j] == ci && (ci != 0 || axis[e])) {
                int pj = g_parent[j];
                if (pj == ri) continue;          // same component already
                int rj;
                if (pj == memo_p) {
                    rj = memo_r;                 // memo hit: skip find chain
                } else {
                    rj = find_root(pj);
                    memo_p = pj; memo_r = rj;
                }
                if (rj != ri) {
                    ri = unite_roots(ri, rj);
                    memo_r = ri;                 // rj now merged into ri
                }
            }
        }
    }
}

// ---------------------------------------------------------------------------
// K6 (fused): fixpoint-check (min-prop insurance, iteration 0) + wrapped
// edge accumulation, sharing one 26-neighbor stencil read.
//  * check: label-min over same-cat neighbors + pointer jump; any repair
//    does atomicMin and raises g_flag[1] (UF can only split, so the min-prop
//    fixpoint provably equals the true labels; empirically no repair fires).
//  * edges: for different-label neighbor pairs, emulate int32-wrapped keys
//    (early gate on base = L*N mod 2^32). If a repair fired anywhere, the
//    guarded fix kernels below redo the edge pass on final labels.
// ---------------------------------------------------------------------------
__global__ void k_edge_check() {
    int i = blockIdx.x * blockDim.x + threadIdx.x;   // exact grid
    int x = i % WW;
    int t = i / WW;
    int y = t % HH;
    int z = t / HH;
    int ci = g_paired[i];
    int L = g_parent[i];
    int best = L;
    unsigned base = (unsigned)L * (unsigned)NN;
    bool edge_on = (base < SENTW) || (base >= (0xFFFFFFFFu - (unsigned)NN));

    const int off[26][3] = {
        {-1,-1,-1},{-1,-1,0},{-1,-1,1},{-1,0,-1},{-1,0,0},{-1,0,1},
        {-1,1,-1},{-1,1,0},{-1,1,1},
        {0,-1,-1},{0,-1,0},{0,-1,1},{0,0,-1},{0,0,1},
        {0,1,-1},{0,1,0},{0,1,1},
        {1,-1,-1},{1,-1,0},{1,-1,1},{1,0,-1},{1,0,0},{1,0,1},
        {1,1,-1},{1,1,0},{1,1,1}};
    const bool axis[26] = {
        false,false,false,false,true,false,false,false,false,
        false,true,false,true,true,false,true,false,
        false,false,false,false,true,false,false,false,false};
#pragma unroll
    for (int k = 0; k < 26; k++) {
        int zz = z + off[k][0];
        int yy = y + off[k][1];
        int xx = x + off[k][2];
        if ((unsigned)zz < DD && (unsigned)yy < HH && (unsigned)xx < WW) {
            int j = (zz * HH + yy) * WW + xx;
            int nl = g_parent[j];
            // fixpoint check (same category only)
            if (g_paired[j] == ci && (ci != 0 || axis[k])) {
                if (nl < best) best = nl;
            }
            // wrapped-edge accumulation (different labels, any category)
            if (edge_on && nl != L) {
                unsigned kw = base + (unsigned)nl;       // wraps mod 2^32
                if (kw < SENTW) {
                    int s = (int)(kw / (unsigned)NN);    // <= 334
                    int d = (int)(kw % (unsigned)NN);
                    int cat = g_paired[d];
                    if (cat == 3) {
                        if (d < g_tpmin[s]) atomicMin(&g_tpmin[s], d);
                        if (d > g_tpmax[s]) atomicMax(&g_tpmax[s], d);
                    } else if (cat == 0) {
                        if (d < g_tnmin[s]) atomicMin(&g_tnmin[s], d);
                        if (d > g_tnmax[s]) atomicMax(&g_tnmax[s], d);
                    }
                }
            }
        }
    }
    int jc = g_parent[L];          // pointer jump (same-component index)
    if (jc < best) best = jc;
    if (best < L) {                // lost union -> repair + raise flag
        atomicMin(&g_parent[i], best);
        g_flag[1] = 1;
    }
}

// K7: insurance min-prop iterations (early-exit when no repair occurred)
__global__ void k_prop(int it) {
    if (g_flag[it] == 0) return;
    int i = blockIdx.x * blockDim.x + threadIdx.x;   // exact grid
    int x = i % WW;
    int t = i / WW;
    int y = t % HH;
    int z = t / HH;
    int ci = g_paired[i];
    int cur = g_parent[i];
    int best = cur;

    const int off[26][3] = {
        {-1,-1,-1},{-1,-1,0},{-1,-1,1},{-1,0,-1},{-1,0,0},{-1,0,1},
        {-1,1,-1},{-1,1,0},{-1,1,1},
        {0,-1,-1},{0,-1,0},{0,-1,1},{0,0,-1},{0,0,1},
        {0,1,-1},{0,1,0},{0,1,1},
        {1,-1,-1},{1,-1,0},{1,-1,1},{1,0,-1},{1,0,0},{1,0,1},
        {1,1,-1},{1,1,0},{1,1,1}};
    const bool axis[26] = {
        false,false,false,false,true,false,false,false,false,
        false,true,false,true,true,false,true,false,
        false,false,false,false,true,false,false,false,false};
#pragma unroll
    for (int k = 0; k < 26; k++) {
        int zz = z + off[k][0];
        int yy = y + off[k][1];
        int xx = x + off[k][2];
        if ((unsigned)zz < DD && (unsigned)yy < HH && (unsigned)xx < WW) {
            int j = (zz * HH + yy) * WW + xx;
            if (g_paired[j] == ci && (ci != 0 || axis[k])) {
                int lj = g_parent[j];
                if (lj < best) best = lj;
            }
        }
    }
    int jc = g_parent[cur];
    if (jc < best) best = jc;
    if (best < cur) {
        atomicMin(&g_parent[i], best);
        g_flag[it + 1] = 1;
    }
}

// K8/K9: guarded edge redo if any repair fired (labels changed after the
// fused pass). Inactive in the expected case (~3us each).
__global__ void k_fixzero() {
    if (g_flag[1] == 0) return;
    int i = threadIdx.x;
    if (i < SMAX) {
        g_tpmin[i] = IMAX; g_tnmin[i] = IMAX;
        g_tpmax[i] = -1;   g_tnmax[i] = -1;
    }
}
__global__ void k_edges_fix() {
    if (g_flag[1] == 0) return;
    int i = blockIdx.x * blockDim.x + threadIdx.x;   // exact grid
    int L = g_parent[i];
    unsigned base = (unsigned)L * (unsigned)NN;
    if (base >= SENTW && base < (0xFFFFFFFFu - (unsigned)NN)) return;
    int x = i % WW;
    int t = i / WW;
    int y = t % HH;
    int z = t / HH;
#pragma unroll
    for (int dz = -1; dz <= 1; dz++)
#pragma unroll
        for (int dy = -1; dy <= 1; dy++)
#pragma unroll
            for (int dx = -1; dx <= 1; dx++) {
                if (dz == 0 && dy == 0 && dx == 0) continue;
                int zz = z + dz, yy = y + dy, xx = x + dx;
                if ((unsigned)zz < DD && (unsigned)yy < HH && (unsigned)xx < WW) {
                    int j = (zz * HH + yy) * WW + xx;
                    int nl = g_parent[j];
                    if (nl != L) {
                        unsigned kw = base + (unsigned)nl;
                        if (kw < SENTW) {
                            int s = (int)(kw / (unsigned)NN);
                            int d = (int)(kw % (unsigned)NN);
                            int cat = g_paired[d];
                            if (cat == 3) {
                                if (d < g_tpmin[s]) atomicMin(&g_tpmin[s], d);
                                if (d > g_tpmax[s]) atomicMax(&g_tpmax[s], d);
                            } else if (cat == 0) {
                                if (d < g_tnmin[s]) atomicMin(&g_tnmin[s], d);
                                if (d > g_tnmax[s]) atomicMax(&g_tnmax[s], d);
                            }
                        }
                    }
                }
            }
}

// ---------------------------------------------------------------------------
// K10: critical voxels -> per-label (sum of (p-g)^2, count), warp-aggregated
// via match groups; reduction iterates only the group's set bits (legal:
// every lane of a group has the same mask and trip count).
// ---------------------------------------------------------------------------
__global__ void k_crit(const float* __restrict__ pred) {
    int i = blockIdx.x * blockDim.x + threadIdx.x;   // exact grid
    int c = g_paired[i];
    bool crit = false;
    int li = -1;
    float v = 0.0f;
    if (c == 1 || c == 2) {
        li = g_parent[i];
        bool ok = false;
        if (li < SMAX)
            ok = (g_tpmin[li] == g_tpmax[li]) && (g_tnmin[li] == g_tnmax[li]);
        if (!ok) {
            float p0 = pred[i];
            float p1 = pred[NN + i];
            float m  = fmaxf(p0, p1);
            float e0 = expf(p0 - m);
            float e1 = expf(p1 - m);
            float p  = e1 / (e0 + e1);
            float g = (c == 2) ? 1.0f : 0.0f;
            float d = p - g;
            v = d * d;
            crit = true;
        }
    }
    int key = crit ? li : -1;
    unsigned grp = __match_any_sync(0xffffffffu, key);
    if (crit) {
        int lane = threadIdx.x & 31;
        int leader = __ffs(grp) - 1;
        float sum = v;
        int cnt = __popc(grp);
        unsigned m = grp & ~(1u << lane);
        while (m) {                         // |grp|-1 iterations, same for all
            int l = __ffs(m) - 1;
            m &= m - 1;
            sum += __shfl_sync(grp, v, l);
        }
        if (lane == leader) {
            atomicAdd(&g_lsum[key], sum);
            atomicAdd(&g_ccnt[key], cnt);
        }
    }
}

// ---------------------------------------------------------------------------
// K11: reg_sum = sum lsum/ccnt over critical labels; n_reg = #(ccnt>0)
// ---------------------------------------------------------------------------
__global__ void k_reduce() {
    __shared__ float ssum[256];
    __shared__ int   scnt[256];
    int i = blockIdx.x * blockDim.x + threadIdx.x;
    float rs = 0.0f;
    int nr = 0;
    int cc = g_ccnt[i];
    if (cc > 0) { rs = g_lsum[i] / (float)cc; nr = 1; }
    ssum[threadIdx.x] = rs;
    scnt[threadIdx.x] = nr;
    __syncthreads();
    for (int s = 128; s > 0; s >>= 1) {
        if (threadIdx.x < s) {
            ssum[threadIdx.x] += ssum[threadIdx.x + s];
            scnt[threadIdx.x] += scnt[threadIdx.x + s];
        }
        __syncthreads();
    }
    if (threadIdx.x == 0) {
        if (ssum[0] != 0.0f) atomicAdd(&g_regsum, ssum[0]);
        if (scnt[0] != 0)    atomicAdd(&g_nreg, scnt[0]);
    }
}

__global__ void k_final(float* out) {
    if (threadIdx.x == 0 && blockIdx.x == 0) {
        int n = g_nreg;
        out[0] = (n > 0) ? (g_regsum / (float)n) : 0.0f;
    }
}

// ---------------------------------------------------------------------------
extern "C" void kernel_launch(void* const* d_in, const int* in_sizes, int n_in,
                              void* d_out, int out_size) {
    const float* pred = (const float*)d_in[0];   // (1,2,64,112,112) float32
    const int*   tgt  = (const int*)d_in[1];     // (1,64,112,112) int32
    if (n_in >= 2 && in_sizes[0] == NN && in_sizes[1] == 2 * NN) {
        pred = (const float*)d_in[1];
        tgt  = (const int*)d_in[0];
    }
    float* out = (float*)d_out;

    const int T = 256;
    const int G = NN / T;          // 3136, exact

    k_init<<<G, T>>>(pred, tgt);   // 1
    k_hook<<<G, T>>>();            // 2
    k_flatten<<<G, T>>>();         // 3
    k_union<<<G, T>>>();           // 4  <- profiled slot
    k_flatten<<<G, T>>>();         // 5
    k_edge_check<<<G, T>>>();      // 6  (fused fixpoint check + edges)
    k_prop<<<G, T>>>(1);           // 7  insurance (early-exit)
    k_prop<<<G, T>>>(2);           // 8  insurance (early-exit)
    k_fixzero<<<1, 512>>>();       // 9  guarded
    k_edges_fix<<<G, T>>>();       // 10 guarded
    k_crit<<<G, T>>>(pred);        // 11
    k_reduce<<<G, T>>>();          // 12
    k_final<<<1, 32>>>(out);       // 13
}